// round 1
// baseline (speedup 1.0000x reference)
#include <cuda_runtime.h>
#include <math.h>

#define BB 8
#define TT 256
#define DD 1024
#define HH 512
#define SS 32896      // T*(T+1)/2
#define K_TOP 512
#define NUM_GOLD 10
#define NEGF (-1e20f)

// ---------------- scratch (no allocation allowed) ----------------
__device__ float d_hs[BB * TT * HH];        // 4 MB
__device__ float d_he[BB * TT * HH];        // 4 MB
__device__ float d_scores[BB * SS];         // ~1 MB
__device__ int   d_topidx[BB * K_TOP];
__device__ float d_toplog[BB * K_TOP];
__device__ float d_losspart[BB];

// =================================================================
// GEMM + bias:  C[b*T+t, h] = sum_d X[b*T+t, d] * W[d, h] + bias[h]
// M=2048, N=512, K=1024.  blockIdx.z selects (W_start,b_start)->d_hs
// or (W_end,b_end)->d_he.  BM=BN=128, BK=8, 256 threads, 8x8/thread.
// =================================================================
__global__ void __launch_bounds__(256)
gemm_bias_kernel(const float* __restrict__ X,
                 const float* __restrict__ Ws, const float* __restrict__ bs,
                 const float* __restrict__ We, const float* __restrict__ be)
{
    const float* W    = blockIdx.z ? We : Ws;
    const float* bias = blockIdx.z ? be : bs;
    float*       C    = blockIdx.z ? d_he : d_hs;

    __shared__ float As[8][128];
    __shared__ float Bs[8][128];

    const int tid = threadIdx.x;
    const int m0  = blockIdx.y * 128;
    const int n0  = blockIdx.x * 128;

    const int aRow = tid >> 1;            // 0..127
    const int aCol = (tid & 1) * 4;       // 0 or 4
    const int bRow = tid >> 5;            // 0..7
    const int bCol = (tid & 31) * 4;      // 0..124

    const int ty = tid >> 4;              // 0..15
    const int tx = tid & 15;              // 0..15

    float acc[8][8];
#pragma unroll
    for (int i = 0; i < 8; i++)
#pragma unroll
        for (int j = 0; j < 8; j++) acc[i][j] = 0.f;

    for (int k0 = 0; k0 < DD; k0 += 8) {
        float4 av = *(const float4*)&X[(size_t)(m0 + aRow) * DD + k0 + aCol];
        As[aCol + 0][aRow] = av.x;
        As[aCol + 1][aRow] = av.y;
        As[aCol + 2][aRow] = av.z;
        As[aCol + 3][aRow] = av.w;
        float4 bv = *(const float4*)&W[(size_t)(k0 + bRow) * HH + n0 + bCol];
        *(float4*)&Bs[bRow][bCol] = bv;
        __syncthreads();

#pragma unroll
        for (int kk = 0; kk < 8; kk++) {
            float4 a0 = *(float4*)&As[kk][ty * 8];
            float4 a1 = *(float4*)&As[kk][ty * 8 + 4];
            float4 b0 = *(float4*)&Bs[kk][tx * 8];
            float4 b1 = *(float4*)&Bs[kk][tx * 8 + 4];
            float am[8] = {a0.x, a0.y, a0.z, a0.w, a1.x, a1.y, a1.z, a1.w};
            float bn[8] = {b0.x, b0.y, b0.z, b0.w, b1.x, b1.y, b1.z, b1.w};
#pragma unroll
            for (int i = 0; i < 8; i++)
#pragma unroll
                for (int j = 0; j < 8; j++)
                    acc[i][j] = fmaf(am[i], bn[j], acc[i][j]);
        }
        __syncthreads();
    }

#pragma unroll
    for (int i = 0; i < 8; i++) {
        int row = m0 + ty * 8 + i;
#pragma unroll
        for (int j = 0; j < 8; j += 4) {
            int col = n0 + tx * 8 + j;
            float4 o;
            o.x = acc[i][j + 0] + bias[col + 0];
            o.y = acc[i][j + 1] + bias[col + 1];
            o.z = acc[i][j + 2] + bias[col + 2];
            o.w = acc[i][j + 3] + bias[col + 3];
            *(float4*)&C[(size_t)row * HH + col] = o;
        }
    }
}

// =================================================================
// Span scoring:  score(i,j) = sum_h relu(hs[i,h]+he[j,h])*w[h] + b
// Tiles of 32x32 spans, h chunked by 128 through smem.
// grid = (36 upper-tri tiles, B), 256 threads, 2x2 spans/thread.
// =================================================================
__device__ __forceinline__ float rdot4(float4 h, float4 e, float4 w)
{
    return fmaxf(h.x + e.x, 0.f) * w.x + fmaxf(h.y + e.y, 0.f) * w.y
         + fmaxf(h.z + e.z, 0.f) * w.z + fmaxf(h.w + e.w, 0.f) * w.w;
}

__global__ void __launch_bounds__(256)
score_kernel(const int* __restrict__ input_mask,
             const float* __restrict__ w_score,
             const float* __restrict__ b_score)
{
    const int b = blockIdx.y;
    int ti = 0, tj = 0;
    {
        int rem = blockIdx.x;
        for (int r = 0; r < 8; r++) {
            int cnt = 8 - r;
            if (rem < cnt) { ti = r; tj = r + rem; break; }
            rem -= cnt;
        }
    }

    __shared__ float hsS[32][132];
    __shared__ float heS[32][132];
    __shared__ float wS[128];

    const int i0 = ti * 32, j0 = tj * 32;
    const int tid = threadIdx.x;
    const int x = tid & 15, y = tid >> 4;

    const float* hsBase = d_hs + ((size_t)b * TT + i0) * HH;
    const float* heBase = d_he + ((size_t)b * TT + j0) * HH;

    float acc00 = 0.f, acc01 = 0.f, acc10 = 0.f, acc11 = 0.f;

    for (int ch = 0; ch < HH; ch += 128) {
        __syncthreads();
        if (tid < 32)
            *(float4*)&wS[tid * 4] = *(const float4*)&w_score[ch + tid * 4];
#pragma unroll
        for (int q = 0; q < 4; q++) {
            int idx = tid + q * 256;
            int r = idx >> 5;
            int c4 = (idx & 31) * 4;
            *(float4*)&hsS[r][c4] = *(const float4*)&hsBase[(size_t)r * HH + ch + c4];
            *(float4*)&heS[r][c4] = *(const float4*)&heBase[(size_t)r * HH + ch + c4];
        }
        __syncthreads();

#pragma unroll 4
        for (int c = 0; c < 128; c += 4) {
            float4 w4 = *(float4*)&wS[c];
            float4 hA = *(float4*)&hsS[y][c];
            float4 hB = *(float4*)&hsS[y + 16][c];
            float4 eA = *(float4*)&heS[x][c];
            float4 eB = *(float4*)&heS[x + 16][c];
            acc00 += rdot4(hA, eA, w4);
            acc01 += rdot4(hA, eB, w4);
            acc10 += rdot4(hB, eA, w4);
            acc11 += rdot4(hB, eB, w4);
        }
    }

    const float bsc = *b_score;
    const int iA = i0 + y, iB = i0 + y + 16;
    const int jA = j0 + x, jB = j0 + x + 16;

    const int* mb = input_mask + b * TT;
    float* sb = d_scores + (size_t)b * SS;

    // tri index: base(i) = (2*i*T - i*i + i)/2 ; s = base(i) + (j-i)
    #define EMIT(ii, jj, av)                                              \
        if ((jj) >= (ii)) {                                               \
            int s = (2 * (ii) * TT - (ii) * (ii) + (ii)) / 2 + ((jj) - (ii)); \
            bool ok = mb[(ii)] && mb[(jj)];                               \
            sb[s] = ok ? ((av) + bsc) : NEGF;                             \
        }
    EMIT(iA, jA, acc00)
    EMIT(iA, jB, acc01)
    EMIT(iB, jA, acc10)
    EMIT(iB, jB, acc11)
    #undef EMIT
}

// =================================================================
// Top-K per batch: radix select (4x8-bit) + ordered selection scan.
// Matches jax top_k tie semantics (lowest index first among equals),
// indices emitted ascending.  One block of 1024 threads per batch.
// =================================================================
__device__ __forceinline__ unsigned fkey(float f)
{
    unsigned u = __float_as_uint(f);
    return (u & 0x80000000u) ? ~u : (u | 0x80000000u);
}

__global__ void __launch_bounds__(1024)
topk_kernel()
{
    const int b = blockIdx.x;
    const float* sc = d_scores + (size_t)b * SS;
    const int tid = threadIdx.x;

    __shared__ unsigned hist[256];
    __shared__ unsigned sh_prefix;
    __shared__ int sh_R;

    unsigned prefix = 0, prefMask = 0;
    int R = K_TOP;

    for (int shift = 24; shift >= 0; shift -= 8) {
        for (int i = tid; i < 256; i += 1024) hist[i] = 0u;
        __syncthreads();
        for (int s = tid; s < SS; s += 1024) {
            unsigned u = fkey(sc[s]);
            if ((u & prefMask) == prefix)
                atomicAdd(&hist[(u >> shift) & 255u], 1u);
        }
        __syncthreads();
        if (tid == 0) {
            int rem = R;
            unsigned bsel = 0;
            for (int bb = 255; bb >= 0; bb--) {
                int c = (int)hist[bb];
                if (c >= rem) { bsel = (unsigned)bb; break; }
                rem -= c;
            }
            sh_prefix = prefix | (bsel << shift);
            sh_R = rem;
        }
        __syncthreads();
        prefix = sh_prefix;
        R = sh_R;
        prefMask |= (0xFFu << shift);
        __syncthreads();
    }

    const unsigned thresh = prefix;   // key of K-th largest
    const int numEqTake = R;          // equals to take (lowest indices)

    __shared__ int wg[32], weq[32], exg[32], exe[32];
    __shared__ int runG, runE, totG, totE;
    if (tid == 0) { runG = 0; runE = 0; }
    __syncthreads();

    const int lane = tid & 31, wid = tid >> 5;

    for (int s0 = 0; s0 < SS; s0 += 1024) {
        int s = s0 + tid;
        bool g = false, e = false;
        float val = 0.f;
        if (s < SS) {
            val = sc[s];
            unsigned u = fkey(val);
            g = (u > thresh);
            e = (u == thresh);
        }
        unsigned bg = __ballot_sync(0xffffffffu, g);
        unsigned be = __ballot_sync(0xffffffffu, e);
        unsigned lt = (lane == 0) ? 0u : (0xffffffffu >> (32 - lane));
        int mg = __popc(bg & lt);
        int me = __popc(be & lt);
        if (lane == 0) { wg[wid] = __popc(bg); weq[wid] = __popc(be); }
        __syncthreads();
        if (tid == 0) {
            int ag = 0, ae = 0;
            for (int wdx = 0; wdx < 32; wdx++) {
                exg[wdx] = ag; exe[wdx] = ae;
                ag += wg[wdx]; ae += weq[wdx];
            }
            totG = ag; totE = ae;
        }
        __syncthreads();
        if (s < SS && (g || e)) {
            int gBefore = runG + exg[wid] + mg;
            int eBefore = runE + exe[wid] + me;
            bool sel = g || (e && eBefore < numEqTake);
            if (sel) {
                int pos = gBefore + min(eBefore, numEqTake);
                d_topidx[b * K_TOP + pos] = s;
                d_toplog[b * K_TOP + pos] = val;
            }
        }
        __syncthreads();
        if (tid == 0) { runG += totG; runE += totE; }
        __syncthreads();
    }
}

// =================================================================
// Finalize: probs + per-batch BCE partial sums
// =================================================================
__global__ void __launch_bounds__(512)
finalize_kernel(const int* __restrict__ answer_spans, float* __restrict__ out)
{
    const int b = blockIdx.x;
    const int k = threadIdx.x;

    __shared__ int gold[NUM_GOLD];
    __shared__ float red[512];

    if (k < NUM_GOLD) {
        int s0 = answer_spans[(b * NUM_GOLD + k) * 2 + 0];
        int e0 = answer_spans[(b * NUM_GOLD + k) * 2 + 1];
        int idx = (2 * s0 * TT - s0 * s0 + s0) / 2 + (e0 - s0);
        gold[k] = (s0 >= 0) ? idx : -1;
    }
    __syncthreads();

    int s = d_topidx[b * K_TOP + k];
    float l = d_toplog[b * K_TOP + k];
    float m = (l > -1e19f) ? 1.f : 0.f;

    float pred = 0.f;
#pragma unroll
    for (int g = 0; g < NUM_GOLD; g++)
        if (gold[g] == s) pred = 1.f;

    float prob = (1.f / (1.f + expf(-l))) * m;
    out[b * K_TOP + k] = prob;

    float bce = fmaxf(l, 0.f) - l * pred + log1pf(expf(-fabsf(l)));
    red[k] = m * bce;
    __syncthreads();
    for (int st = 256; st > 0; st >>= 1) {
        if (k < st) red[k] += red[k + st];
        __syncthreads();
    }
    if (k == 0) d_losspart[b] = red[0];
}

__global__ void sum_loss_kernel(float* __restrict__ out)
{
    float ssum = 0.f;
    for (int b = 0; b < BB; b++) ssum += d_losspart[b];
    out[BB * K_TOP] = ssum;
}

// =================================================================
// Launch
// =================================================================
extern "C" void kernel_launch(void* const* d_in, const int* in_sizes, int n_in,
                              void* d_out, int out_size)
{
    const float* inputs       = (const float*)d_in[0];
    const int*   input_mask   = (const int*)d_in[1];
    const int*   answer_spans = (const int*)d_in[2];
    const float* W_start      = (const float*)d_in[3];
    const float* b_start      = (const float*)d_in[4];
    const float* W_end        = (const float*)d_in[5];
    const float* b_end        = (const float*)d_in[6];
    const float* w_score      = (const float*)d_in[7];
    const float* b_score      = (const float*)d_in[8];
    float* out = (float*)d_out;

    dim3 gGemm(HH / 128, (BB * TT) / 128, 2);   // (4, 16, 2)
    gemm_bias_kernel<<<gGemm, 256>>>(inputs, W_start, b_start, W_end, b_end);

    dim3 gScore(36, BB);
    score_kernel<<<gScore, 256>>>(input_mask, w_score, b_score);

    topk_kernel<<<BB, 1024>>>();

    finalize_kernel<<<BB, 512>>>(answer_spans, out);

    sum_loss_kernel<<<1, 1>>>(out);
}

// round 4
// speedup vs baseline: 1.6624x; 1.6624x over previous
#include <cuda_runtime.h>
#include <cuda_bf16.h>
#include <cstdint>
#include <math.h>

#define BB 8
#define TT 256
#define DD 1024
#define HH 512
#define SS 32896      // T*(T+1)/2
#define K_TOP 512
#define NUM_GOLD 10
#define NEGF (-1e20f)

#define M_TOT (BB * TT)   // 2048

// ---------------- scratch (no allocation allowed) ----------------
__device__ float d_hs[M_TOT * HH];              // 4 MB
__device__ float d_he[M_TOT * HH];              // 4 MB
__device__ float d_scores[BB * SS];             // ~1 MB
__device__ int   d_topidx[BB * K_TOP];
__device__ float d_toplog[BB * K_TOP];
__device__ float d_losspart[BB];

__device__ __nv_bfloat16 d_Xh[M_TOT * DD];      // 4 MB
__device__ __nv_bfloat16 d_Xl[M_TOT * DD];      // 4 MB
__device__ __nv_bfloat16 d_Wth[2][HH * DD];     // W^T hi, [n,k]
__device__ __nv_bfloat16 d_Wtl[2][HH * DD];     // W^T lo, [n,k]

// ======================= helpers ============================
__device__ __forceinline__ uint32_t smem_u32(const void* p)
{
    uint32_t a;
    asm("{ .reg .u64 t; cvta.to.shared.u64 t, %1; cvt.u32.u64 %0, t; }"
        : "=r"(a) : "l"(p));
    return a;
}

#define LDSM_X4(r0, r1, r2, r3, addr) \
    asm volatile("ldmatrix.sync.aligned.m8n8.x4.shared.b16 {%0,%1,%2,%3}, [%4];" \
                 : "=r"(r0), "=r"(r1), "=r"(r2), "=r"(r3) : "r"(addr))

#define MMA16816(d, a0, a1, a2, a3, b0, b1) \
    asm volatile("mma.sync.aligned.m16n8k16.row.col.f32.bf16.bf16.f32 " \
                 "{%0,%1,%2,%3}, {%4,%5,%6,%7}, {%8,%9}, {%0,%1,%2,%3};" \
                 : "+f"((d)[0]), "+f"((d)[1]), "+f"((d)[2]), "+f"((d)[3]) \
                 : "r"(a0), "r"(a1), "r"(a2), "r"(a3), "r"(b0), "r"(b1))

#define CP_ASYNC16(saddr, gaddr) \
    asm volatile("cp.async.cg.shared.global [%0], [%1], 16;" \
                 :: "r"(saddr), "l"(gaddr))
#define CP_COMMIT()  asm volatile("cp.async.commit_group;" ::: "memory")
#define CP_WAIT1()   asm volatile("cp.async.wait_group 1;" ::: "memory")
#define CP_WAIT0()   asm volatile("cp.async.wait_group 0;" ::: "memory")

// =================================================================
// Conversion kernels: fp32 -> (bf16 hi, bf16 lo) split
// =================================================================
__global__ void __launch_bounds__(256)
convert_x_kernel(const float* __restrict__ X)
{
    int i = blockIdx.x * 256 + threadIdx.x;      // float4 index, total 524288
    float4 v = ((const float4*)X)[i];
    __nv_bfloat16 h0 = __float2bfloat16_rn(v.x);
    __nv_bfloat16 h1 = __float2bfloat16_rn(v.y);
    __nv_bfloat16 h2 = __float2bfloat16_rn(v.z);
    __nv_bfloat16 h3 = __float2bfloat16_rn(v.w);
    __nv_bfloat16 l0 = __float2bfloat16_rn(v.x - __bfloat162float(h0));
    __nv_bfloat16 l1 = __float2bfloat16_rn(v.y - __bfloat162float(h1));
    __nv_bfloat16 l2 = __float2bfloat16_rn(v.z - __bfloat162float(h2));
    __nv_bfloat16 l3 = __float2bfloat16_rn(v.w - __bfloat162float(h3));
    ((__nv_bfloat162*)d_Xh)[2 * i]     = __nv_bfloat162(h0, h1);
    ((__nv_bfloat162*)d_Xh)[2 * i + 1] = __nv_bfloat162(h2, h3);
    ((__nv_bfloat162*)d_Xl)[2 * i]     = __nv_bfloat162(l0, l1);
    ((__nv_bfloat162*)d_Xl)[2 * i + 1] = __nv_bfloat162(l2, l3);
}

// transpose W [K=1024, N=512] -> Wt [N, K], split hi/lo
__global__ void __launch_bounds__(256)
convert_w_kernel(const float* __restrict__ Ws, const float* __restrict__ We)
{
    const float* W = blockIdx.z ? We : Ws;
    __nv_bfloat16* oh = d_Wth[blockIdx.z];
    __nv_bfloat16* ol = d_Wtl[blockIdx.z];

    __shared__ float s[32][33];
    const int n0 = blockIdx.x * 32;
    const int k0 = blockIdx.y * 32;
    const int tx = threadIdx.x & 31, ty = threadIdx.x >> 5;   // 32x8

    for (int j = ty; j < 32; j += 8)
        s[j][tx] = W[(size_t)(k0 + j) * HH + n0 + tx];
    __syncthreads();
    for (int j = ty; j < 32; j += 8) {
        float v = s[tx][j];      // W[k0+tx][n0+j]
        __nv_bfloat16 h = __float2bfloat16_rn(v);
        __nv_bfloat16 l = __float2bfloat16_rn(v - __bfloat162float(h));
        size_t o = (size_t)(n0 + j) * DD + k0 + tx;
        oh[o] = h;
        ol[o] = l;
    }
}

// =================================================================
// mma.sync GEMM: C[m, n] = sum_k X[m,k] * W[k,n] + bias[n]
// CTA tile 128x128, BK=64, 8 warps (32x64 each), cp.async 2-stage,
// 3-product bf16 split (hi*hi + hi*lo + lo*hi).
// grid = (N/128=4, M/128=16, 2), 256 threads.
// =================================================================
#define SKW_B 144                        // smem row stride (72 bf16) bytes
#define BUF_BYTES (128 * SKW_B)          // 18432
#define STAGE_BYTES (4 * BUF_BYTES)      // 73728
#define GEMM_SMEM (2 * STAGE_BYTES)      // 147456

__global__ void __launch_bounds__(256, 1)
gemm_mma_kernel(const float* __restrict__ bias_s, const float* __restrict__ bias_e)
{
    extern __shared__ char smem[];
    const int tid = threadIdx.x, wid = tid >> 5, lane = tid & 31;
    const int which = blockIdx.z;
    const int m0 = blockIdx.y * 128, n0 = blockIdx.x * 128;

    const char* gsrc0[4];
    gsrc0[0] = (const char*)(d_Xh + (size_t)m0 * DD);
    gsrc0[1] = (const char*)(d_Xl + (size_t)m0 * DD);
    gsrc0[2] = (const char*)(d_Wth[which] + (size_t)n0 * DD);
    gsrc0[3] = (const char*)(d_Wtl[which] + (size_t)n0 * DD);

    const int lr = tid >> 3;             // 0..31 (row base; +32 per it)
    const int lc = tid & 7;              // 16B column 0..7

    // fragment lane offsets
    const int warp_m = wid & 3, warp_n = wid >> 2;
    const int aRowOff = (warp_m * 32 + (lane & 15)) * SKW_B;
    const int aColOff = (lane >> 4) * 16;
    const int bRowOff = (warp_n * 64 + (lane & 7) + ((lane >> 4) << 3)) * SKW_B;
    const int bColOff = ((lane >> 3) & 1) * 16;

    float acc[2][8][4];
#pragma unroll
    for (int mt = 0; mt < 2; mt++)
#pragma unroll
        for (int nt = 0; nt < 8; nt++)
#pragma unroll
            for (int q = 0; q < 4; q++) acc[mt][nt][q] = 0.f;

    const uint32_t sstage[2] = { smem_u32(smem), smem_u32(smem + STAGE_BYTES) };

    // ---- stage issue (cp.async, 16 LDGSTS per thread) ----
    #define ISSUE_STAGE(c, stg) do {                                          \
        const int kcB = (c) * 128;   /* 64 bf16 = 128 bytes */                \
        _Pragma("unroll")                                                     \
        for (int t = 0; t < 4; t++) {                                         \
            uint32_t sbase = sstage[stg] + t * BUF_BYTES;                     \
            const char* g = gsrc0[t] + kcB;                                   \
            _Pragma("unroll")                                                 \
            for (int it = 0; it < 4; it++) {                                  \
                int r = lr + it * 32;                                         \
                uint32_t sa = sbase + r * SKW_B + lc * 16;                    \
                const char* ga = g + (size_t)r * (DD * 2) + lc * 16;          \
                CP_ASYNC16(sa, ga);                                           \
            }                                                                 \
        }                                                                     \
        CP_COMMIT();                                                          \
    } while (0)

    ISSUE_STAGE(0, 0);

    const int pa[3] = {0, 0, 1};         // A buffer per product (Ah,Ah,Al)
    const int pb[3] = {2, 3, 2};         // B buffer per product (Bh,Bl,Bh)

    for (int c = 0; c < 16; c++) {
        const int stg = c & 1;
        if (c + 1 < 16) { ISSUE_STAGE(c + 1, stg ^ 1); CP_WAIT1(); }
        else            { CP_WAIT0(); }
        __syncthreads();

        const uint32_t sb = sstage[stg];
#pragma unroll
        for (int kk = 0; kk < 4; kk++) {
#pragma unroll
            for (int p = 0; p < 3; p++) {
                const uint32_t ab = sb + pa[p] * BUF_BYTES + aRowOff + kk * 32 + aColOff;
                uint32_t a0[4], a1[4];
                LDSM_X4(a0[0], a0[1], a0[2], a0[3], ab);
                LDSM_X4(a1[0], a1[1], a1[2], a1[3], ab + 16 * SKW_B);

                const uint32_t bbase = sb + pb[p] * BUF_BYTES + bRowOff + kk * 32 + bColOff;
                uint32_t b[4][4];
#pragma unroll
                for (int ntp = 0; ntp < 4; ntp++)
                    LDSM_X4(b[ntp][0], b[ntp][1], b[ntp][2], b[ntp][3],
                            bbase + ntp * 16 * SKW_B);

#pragma unroll
                for (int nt = 0; nt < 8; nt++) {
                    const uint32_t bb0 = b[nt >> 1][(nt & 1) * 2];
                    const uint32_t bb1 = b[nt >> 1][(nt & 1) * 2 + 1];
                    MMA16816(acc[0][nt], a0[0], a0[1], a0[2], a0[3], bb0, bb1);
                    MMA16816(acc[1][nt], a1[0], a1[1], a1[2], a1[3], bb0, bb1);
                }
            }
        }
        __syncthreads();
    }

    // ---- epilogue: bias + store fp32 ----
    const float* bias = which ? bias_e : bias_s;
    float* C = which ? d_he : d_hs;
    const int row0 = m0 + warp_m * 32 + (lane >> 2);
    const int col0 = n0 + warp_n * 64 + (lane & 3) * 2;
#pragma unroll
    for (int mt = 0; mt < 2; mt++) {
#pragma unroll
        for (int nt = 0; nt < 8; nt++) {
            const int row = row0 + mt * 16;
            const int col = col0 + nt * 8;
            const float b0 = bias[col], b1 = bias[col + 1];
            float2 v0 = { acc[mt][nt][0] + b0, acc[mt][nt][1] + b1 };
            float2 v1 = { acc[mt][nt][2] + b0, acc[mt][nt][3] + b1 };
            *(float2*)&C[(size_t)row * HH + col] = v0;
            *(float2*)&C[(size_t)(row + 8) * HH + col] = v1;
        }
    }
}

// =================================================================
// Span scoring:  score(i,j) = sum_h relu(hs[i,h]+he[j,h])*w[h] + b
// =================================================================
__device__ __forceinline__ float rdot4(float4 h, float4 e, float4 w)
{
    return fmaxf(h.x + e.x, 0.f) * w.x + fmaxf(h.y + e.y, 0.f) * w.y
         + fmaxf(h.z + e.z, 0.f) * w.z + fmaxf(h.w + e.w, 0.f) * w.w;
}

__global__ void __launch_bounds__(256)
score_kernel(const int* __restrict__ input_mask,
             const float* __restrict__ w_score,
             const float* __restrict__ b_score)
{
    const int b = blockIdx.y;
    int ti = 0, tj = 0;
    {
        int rem = blockIdx.x;
        for (int r = 0; r < 8; r++) {
            int cnt = 8 - r;
            if (rem < cnt) { ti = r; tj = r + rem; break; }
            rem -= cnt;
        }
    }

    __shared__ float hsS[32][132];
    __shared__ float heS[32][132];
    __shared__ float wS[128];

    const int i0 = ti * 32, j0 = tj * 32;
    const int tid = threadIdx.x;
    const int x = tid & 15, y = tid >> 4;

    const float* hsBase = d_hs + ((size_t)b * TT + i0) * HH;
    const float* heBase = d_he + ((size_t)b * TT + j0) * HH;

    float acc00 = 0.f, acc01 = 0.f, acc10 = 0.f, acc11 = 0.f;

    for (int ch = 0; ch < HH; ch += 128) {
        __syncthreads();
        if (tid < 32)
            *(float4*)&wS[tid * 4] = *(const float4*)&w_score[ch + tid * 4];
#pragma unroll
        for (int q = 0; q < 4; q++) {
            int idx = tid + q * 256;
            int r = idx >> 5;
            int c4 = (idx & 31) * 4;
            *(float4*)&hsS[r][c4] = *(const float4*)&hsBase[(size_t)r * HH + ch + c4];
            *(float4*)&heS[r][c4] = *(const float4*)&heBase[(size_t)r * HH + ch + c4];
        }
        __syncthreads();

#pragma unroll 4
        for (int c = 0; c < 128; c += 4) {
            float4 w4 = *(float4*)&wS[c];
            float4 hA = *(float4*)&hsS[y][c];
            float4 hB = *(float4*)&hsS[y + 16][c];
            float4 eA = *(float4*)&heS[x][c];
            float4 eB = *(float4*)&heS[x + 16][c];
            acc00 += rdot4(hA, eA, w4);
            acc01 += rdot4(hA, eB, w4);
            acc10 += rdot4(hB, eA, w4);
            acc11 += rdot4(hB, eB, w4);
        }
    }

    const float bsc = *b_score;
    const int iA = i0 + y, iB = i0 + y + 16;
    const int jA = j0 + x, jB = j0 + x + 16;

    const int* mb = input_mask + b * TT;
    float* sb = d_scores + (size_t)b * SS;

    #define EMIT(ii, jj, av)                                                  \
        if ((jj) >= (ii)) {                                                   \
            int s = (2 * (ii) * TT - (ii) * (ii) + (ii)) / 2 + ((jj) - (ii)); \
            bool ok = mb[(ii)] && mb[(jj)];                                   \
            sb[s] = ok ? ((av) + bsc) : NEGF;                                 \
        }
    EMIT(iA, jA, acc00)
    EMIT(iA, jB, acc01)
    EMIT(iB, jA, acc10)
    EMIT(iB, jB, acc11)
    #undef EMIT
}

// =================================================================
// Top-K per batch: radix select + ordered selection scan
// =================================================================
__device__ __forceinline__ unsigned fkey(float f)
{
    unsigned u = __float_as_uint(f);
    return (u & 0x80000000u) ? ~u : (u | 0x80000000u);
}

__global__ void __launch_bounds__(1024)
topk_kernel()
{
    const int b = blockIdx.x;
    const float* sc = d_scores + (size_t)b * SS;
    const int tid = threadIdx.x;

    __shared__ unsigned hist[256];
    __shared__ unsigned sh_prefix;
    __shared__ int sh_R;

    unsigned prefix = 0, prefMask = 0;
    int R = K_TOP;

    for (int shift = 24; shift >= 0; shift -= 8) {
        for (int i = tid; i < 256; i += 1024) hist[i] = 0u;
        __syncthreads();
        for (int s = tid; s < SS; s += 1024) {
            unsigned u = fkey(sc[s]);
            if ((u & prefMask) == prefix)
                atomicAdd(&hist[(u >> shift) & 255u], 1u);
        }
        __syncthreads();
        if (tid == 0) {
            int rem = R;
            unsigned bsel = 0;
            for (int bb = 255; bb >= 0; bb--) {
                int c = (int)hist[bb];
                if (c >= rem) { bsel = (unsigned)bb; break; }
                rem -= c;
            }
            sh_prefix = prefix | (bsel << shift);
            sh_R = rem;
        }
        __syncthreads();
        prefix = sh_prefix;
        R = sh_R;
        prefMask |= (0xFFu << shift);
        __syncthreads();
    }

    const unsigned thresh = prefix;
    const int numEqTake = R;

    __shared__ int wg[32], weq[32], exg[32], exe[32];
    __shared__ int runG, runE, totG, totE;
    if (tid == 0) { runG = 0; runE = 0; }
    __syncthreads();

    const int lane = tid & 31, wid = tid >> 5;

    for (int s0 = 0; s0 < SS; s0 += 1024) {
        int s = s0 + tid;
        bool g = false, e = false;
        float val = 0.f;
        if (s < SS) {
            val = sc[s];
            unsigned u = fkey(val);
            g = (u > thresh);
            e = (u == thresh);
        }
        unsigned bg = __ballot_sync(0xffffffffu, g);
        unsigned be = __ballot_sync(0xffffffffu, e);
        unsigned lt = (lane == 0) ? 0u : (0xffffffffu >> (32 - lane));
        int mg = __popc(bg & lt);
        int me = __popc(be & lt);
        if (lane == 0) { wg[wid] = __popc(bg); weq[wid] = __popc(be); }
        __syncthreads();
        if (tid == 0) {
            int ag = 0, ae = 0;
            for (int wdx = 0; wdx < 32; wdx++) {
                exg[wdx] = ag; exe[wdx] = ae;
                ag += wg[wdx]; ae += weq[wdx];
            }
            totG = ag; totE = ae;
        }
        __syncthreads();
        if (s < SS && (g || e)) {
            int gBefore = runG + exg[wid] + mg;
            int eBefore = runE + exe[wid] + me;
            bool sel = g || (e && eBefore < numEqTake);
            if (sel) {
                int pos = gBefore + min(eBefore, numEqTake);
                d_topidx[b * K_TOP + pos] = s;
                d_toplog[b * K_TOP + pos] = val;
            }
        }
        __syncthreads();
        if (tid == 0) { runG += totG; runE += totE; }
        __syncthreads();
    }
}

// =================================================================
// Finalize: probs + per-batch BCE partial sums
// =================================================================
__global__ void __launch_bounds__(512)
finalize_kernel(const int* __restrict__ answer_spans, float* __restrict__ out)
{
    const int b = blockIdx.x;
    const int k = threadIdx.x;

    __shared__ int gold[NUM_GOLD];
    __shared__ float red[512];

    if (k < NUM_GOLD) {
        int s0 = answer_spans[(b * NUM_GOLD + k) * 2 + 0];
        int e0 = answer_spans[(b * NUM_GOLD + k) * 2 + 1];
        int idx = (2 * s0 * TT - s0 * s0 + s0) / 2 + (e0 - s0);
        gold[k] = (s0 >= 0) ? idx : -1;
    }
    __syncthreads();

    int s = d_topidx[b * K_TOP + k];
    float l = d_toplog[b * K_TOP + k];
    float m = (l > -1e19f) ? 1.f : 0.f;

    float pred = 0.f;
#pragma unroll
    for (int g = 0; g < NUM_GOLD; g++)
        if (gold[g] == s) pred = 1.f;

    float prob = (1.f / (1.f + expf(-l))) * m;
    out[b * K_TOP + k] = prob;

    float bce = fmaxf(l, 0.f) - l * pred + log1pf(expf(-fabsf(l)));
    red[k] = m * bce;
    __syncthreads();
    for (int st = 256; st > 0; st >>= 1) {
        if (k < st) red[k] += red[k + st];
        __syncthreads();
    }
    if (k == 0) d_losspart[b] = red[0];
}

__global__ void sum_loss_kernel(float* __restrict__ out)
{
    float ssum = 0.f;
    for (int b = 0; b < BB; b++) ssum += d_losspart[b];
    out[BB * K_TOP] = ssum;
}

// =================================================================
// Launch
// =================================================================
extern "C" void kernel_launch(void* const* d_in, const int* in_sizes, int n_in,
                              void* d_out, int out_size)
{
    const float* inputs       = (const float*)d_in[0];
    const int*   input_mask   = (const int*)d_in[1];
    const int*   answer_spans = (const int*)d_in[2];
    const float* W_start      = (const float*)d_in[3];
    const float* b_start      = (const float*)d_in[4];
    const float* W_end        = (const float*)d_in[5];
    const float* b_end        = (const float*)d_in[6];
    const float* w_score      = (const float*)d_in[7];
    const float* b_score      = (const float*)d_in[8];
    float* out = (float*)d_out;

    static int smem_set = 0;
    if (!smem_set) {
        cudaFuncSetAttribute(gemm_mma_kernel,
                             cudaFuncAttributeMaxDynamicSharedMemorySize, GEMM_SMEM);
        smem_set = 1;
    }

    convert_x_kernel<<<(M_TOT * DD / 4) / 256, 256>>>(inputs);

    dim3 gW(HH / 32, DD / 32, 2);
    convert_w_kernel<<<gW, 256>>>(W_start, W_end);

    dim3 gGemm(HH / 128, M_TOT / 128, 2);   // (4, 16, 2)
    gemm_mma_kernel<<<gGemm, 256, GEMM_SMEM>>>(b_start, b_end);

    dim3 gScore(36, BB);
    score_kernel<<<gScore, 256>>>(input_mask, w_score, b_score);

    topk_kernel<<<BB, 1024>>>();

    finalize_kernel<<<BB, 512>>>(answer_spans, out);

    sum_loss_kernel<<<1, 1>>>(out);
}

// round 5
// speedup vs baseline: 1.8791x; 1.1304x over previous
#include <cuda_runtime.h>
#include <cuda_bf16.h>
#include <cstdint>
#include <math.h>

#define BB 8
#define TT 256
#define DD 1024
#define HH 512
#define SS 32896      // T*(T+1)/2 = 32*1028
#define K_TOP 512
#define NUM_GOLD 10
#define NEGF (-1e20f)

#define M_TOT (BB * TT)   // 2048
#define SLICE 1028        // SS / 32

// ---------------- scratch (no allocation allowed) ----------------
__device__ float d_hs[M_TOT * HH];              // 4 MB
__device__ float d_he[M_TOT * HH];              // 4 MB
__device__ float d_spart[4][BB * SS];           // 4.2 MB score partials
__device__ float d_scores[BB * SS];             // ~1 MB
__device__ int   d_topidx[BB * K_TOP];
__device__ float d_toplog[BB * K_TOP];
__device__ float d_losspart[BB];

__device__ unsigned d_hist[BB][256];
__device__ unsigned d_prefix[BB];
__device__ int      d_R[BB];

__device__ __nv_bfloat16 d_Xh[M_TOT * DD];      // 4 MB
__device__ __nv_bfloat16 d_Xl[M_TOT * DD];      // 4 MB
__device__ __nv_bfloat16 d_Wth[2][HH * DD];     // W^T hi, [n,k]
__device__ __nv_bfloat16 d_Wtl[2][HH * DD];     // W^T lo, [n,k]

// ======================= helpers ============================
__device__ __forceinline__ uint32_t smem_u32(const void* p)
{
    uint32_t a;
    asm("{ .reg .u64 t; cvta.to.shared.u64 t, %1; cvt.u32.u64 %0, t; }"
        : "=r"(a) : "l"(p));
    return a;
}

#define LDSM_X4(r0, r1, r2, r3, addr) \
    asm volatile("ldmatrix.sync.aligned.m8n8.x4.shared.b16 {%0,%1,%2,%3}, [%4];" \
                 : "=r"(r0), "=r"(r1), "=r"(r2), "=r"(r3) : "r"(addr))

#define MMA16816(d, a0, a1, a2, a3, b0, b1) \
    asm volatile("mma.sync.aligned.m16n8k16.row.col.f32.bf16.bf16.f32 " \
                 "{%0,%1,%2,%3}, {%4,%5,%6,%7}, {%8,%9}, {%0,%1,%2,%3};" \
                 : "+f"((d)[0]), "+f"((d)[1]), "+f"((d)[2]), "+f"((d)[3]) \
                 : "r"(a0), "r"(a1), "r"(a2), "r"(a3), "r"(b0), "r"(b1))

#define CP_ASYNC16(saddr, gaddr) \
    asm volatile("cp.async.cg.shared.global [%0], [%1], 16;" \
                 :: "r"(saddr), "l"(gaddr))
#define CP_COMMIT()  asm volatile("cp.async.commit_group;" ::: "memory")
#define CP_WAIT1()   asm volatile("cp.async.wait_group 1;" ::: "memory")
#define CP_WAIT0()   asm volatile("cp.async.wait_group 0;" ::: "memory")

// =================================================================
// Conversion kernels: fp32 -> (bf16 hi, bf16 lo) split
// =================================================================
__global__ void __launch_bounds__(256)
convert_x_kernel(const float* __restrict__ X)
{
    int i = blockIdx.x * 256 + threadIdx.x;      // float4 index
    float4 v = ((const float4*)X)[i];
    __nv_bfloat16 h0 = __float2bfloat16_rn(v.x);
    __nv_bfloat16 h1 = __float2bfloat16_rn(v.y);
    __nv_bfloat16 h2 = __float2bfloat16_rn(v.z);
    __nv_bfloat16 h3 = __float2bfloat16_rn(v.w);
    __nv_bfloat16 l0 = __float2bfloat16_rn(v.x - __bfloat162float(h0));
    __nv_bfloat16 l1 = __float2bfloat16_rn(v.y - __bfloat162float(h1));
    __nv_bfloat16 l2 = __float2bfloat16_rn(v.z - __bfloat162float(h2));
    __nv_bfloat16 l3 = __float2bfloat16_rn(v.w - __bfloat162float(h3));
    ((__nv_bfloat162*)d_Xh)[2 * i]     = __nv_bfloat162(h0, h1);
    ((__nv_bfloat162*)d_Xh)[2 * i + 1] = __nv_bfloat162(h2, h3);
    ((__nv_bfloat162*)d_Xl)[2 * i]     = __nv_bfloat162(l0, l1);
    ((__nv_bfloat162*)d_Xl)[2 * i + 1] = __nv_bfloat162(l2, l3);
}

// transpose W [K=1024, N=512] -> Wt [N, K], split hi/lo
__global__ void __launch_bounds__(256)
convert_w_kernel(const float* __restrict__ Ws, const float* __restrict__ We)
{
    const float* W = blockIdx.z ? We : Ws;
    __nv_bfloat16* oh = d_Wth[blockIdx.z];
    __nv_bfloat16* ol = d_Wtl[blockIdx.z];

    __shared__ float s[32][33];
    const int n0 = blockIdx.x * 32;
    const int k0 = blockIdx.y * 32;
    const int tx = threadIdx.x & 31, ty = threadIdx.x >> 5;   // 32x8

    for (int j = ty; j < 32; j += 8)
        s[j][tx] = W[(size_t)(k0 + j) * HH + n0 + tx];
    __syncthreads();
    for (int j = ty; j < 32; j += 8) {
        float v = s[tx][j];      // W[k0+tx][n0+j]
        __nv_bfloat16 h = __float2bfloat16_rn(v);
        __nv_bfloat16 l = __float2bfloat16_rn(v - __bfloat162float(h));
        size_t o = (size_t)(n0 + j) * DD + k0 + tx;
        oh[o] = h;
        ol[o] = l;
    }
}

// =================================================================
// mma.sync GEMM: CTA tile 128x128, BK=64, 8 warps, cp.async 2-stage,
// 3-product bf16 split.  grid = (4, 16, 2), 256 threads.
// =================================================================
#define SKW_B 144                        // smem row stride bytes
#define BUF_BYTES (128 * SKW_B)          // 18432
#define STAGE_BYTES (4 * BUF_BYTES)      // 73728
#define GEMM_SMEM (2 * STAGE_BYTES)      // 147456

__global__ void __launch_bounds__(256, 1)
gemm_mma_kernel(const float* __restrict__ bias_s, const float* __restrict__ bias_e)
{
    extern __shared__ char smem[];
    const int tid = threadIdx.x, wid = tid >> 5, lane = tid & 31;
    const int which = blockIdx.z;
    const int m0 = blockIdx.y * 128, n0 = blockIdx.x * 128;

    const char* gsrc0[4];
    gsrc0[0] = (const char*)(d_Xh + (size_t)m0 * DD);
    gsrc0[1] = (const char*)(d_Xl + (size_t)m0 * DD);
    gsrc0[2] = (const char*)(d_Wth[which] + (size_t)n0 * DD);
    gsrc0[3] = (const char*)(d_Wtl[which] + (size_t)n0 * DD);

    const int lr = tid >> 3;             // 0..31 (row base; +32 per it)
    const int lc = tid & 7;              // 16B column 0..7

    const int warp_m = wid & 3, warp_n = wid >> 2;
    const int aRowOff = (warp_m * 32 + (lane & 15)) * SKW_B;
    const int aColOff = (lane >> 4) * 16;
    const int bRowOff = (warp_n * 64 + (lane & 7) + ((lane >> 4) << 3)) * SKW_B;
    const int bColOff = ((lane >> 3) & 1) * 16;

    float acc[2][8][4];
#pragma unroll
    for (int mt = 0; mt < 2; mt++)
#pragma unroll
        for (int nt = 0; nt < 8; nt++)
#pragma unroll
            for (int q = 0; q < 4; q++) acc[mt][nt][q] = 0.f;

    const uint32_t sstage[2] = { smem_u32(smem), smem_u32(smem + STAGE_BYTES) };

    #define ISSUE_STAGE(c, stg) do {                                          \
        const int kcB = (c) * 128;                                            \
        _Pragma("unroll")                                                     \
        for (int t = 0; t < 4; t++) {                                         \
            uint32_t sbase = sstage[stg] + t * BUF_BYTES;                     \
            const char* g = gsrc0[t] + kcB;                                   \
            _Pragma("unroll")                                                 \
            for (int it = 0; it < 4; it++) {                                  \
                int r = lr + it * 32;                                         \
                uint32_t sa = sbase + r * SKW_B + lc * 16;                    \
                const char* ga = g + (size_t)r * (DD * 2) + lc * 16;          \
                CP_ASYNC16(sa, ga);                                           \
            }                                                                 \
        }                                                                     \
        CP_COMMIT();                                                          \
    } while (0)

    ISSUE_STAGE(0, 0);

    const int pa[3] = {0, 0, 1};
    const int pb[3] = {2, 3, 2};

    for (int c = 0; c < 16; c++) {
        const int stg = c & 1;
        if (c + 1 < 16) { ISSUE_STAGE(c + 1, stg ^ 1); CP_WAIT1(); }
        else            { CP_WAIT0(); }
        __syncthreads();

        const uint32_t sb = sstage[stg];
#pragma unroll
        for (int kk = 0; kk < 4; kk++) {
#pragma unroll
            for (int p = 0; p < 3; p++) {
                const uint32_t ab = sb + pa[p] * BUF_BYTES + aRowOff + kk * 32 + aColOff;
                uint32_t a0[4], a1[4];
                LDSM_X4(a0[0], a0[1], a0[2], a0[3], ab);
                LDSM_X4(a1[0], a1[1], a1[2], a1[3], ab + 16 * SKW_B);

                const uint32_t bbase = sb + pb[p] * BUF_BYTES + bRowOff + kk * 32 + bColOff;
                uint32_t b[4][4];
#pragma unroll
                for (int ntp = 0; ntp < 4; ntp++)
                    LDSM_X4(b[ntp][0], b[ntp][1], b[ntp][2], b[ntp][3],
                            bbase + ntp * 16 * SKW_B);

#pragma unroll
                for (int nt = 0; nt < 8; nt++) {
                    const uint32_t bb0 = b[nt >> 1][(nt & 1) * 2];
                    const uint32_t bb1 = b[nt >> 1][(nt & 1) * 2 + 1];
                    MMA16816(acc[0][nt], a0[0], a0[1], a0[2], a0[3], bb0, bb1);
                    MMA16816(acc[1][nt], a1[0], a1[1], a1[2], a1[3], bb0, bb1);
                }
            }
        }
        __syncthreads();
    }

    const float* bias = which ? bias_e : bias_s;
    float* C = which ? d_he : d_hs;
    const int row0 = m0 + warp_m * 32 + (lane >> 2);
    const int col0 = n0 + warp_n * 64 + (lane & 3) * 2;
#pragma unroll
    for (int mt = 0; mt < 2; mt++) {
#pragma unroll
        for (int nt = 0; nt < 8; nt++) {
            const int row = row0 + mt * 16;
            const int col = col0 + nt * 8;
            const float b0 = bias[col], b1 = bias[col + 1];
            float2 v0 = { acc[mt][nt][0] + b0, acc[mt][nt][1] + b1 };
            float2 v1 = { acc[mt][nt][2] + b0, acc[mt][nt][3] + b1 };
            *(float2*)&C[(size_t)row * HH + col] = v0;
            *(float2*)&C[(size_t)(row + 8) * HH + col] = v1;
        }
    }
}

// =================================================================
// Span scoring, partial over an h-chunk of 128 channels.
// grid = (36 tiles, 4 chunks, 8 batches), 256 threads, 2x2/thread.
// =================================================================
__device__ __forceinline__ float rdot4(float4 h, float4 e, float4 w)
{
    return fmaxf(h.x + e.x, 0.f) * w.x + fmaxf(h.y + e.y, 0.f) * w.y
         + fmaxf(h.z + e.z, 0.f) * w.z + fmaxf(h.w + e.w, 0.f) * w.w;
}

__device__ __forceinline__ void tile_decode(int bx, int& ti, int& tj)
{
    int rem = bx;
    for (int r = 0; r < 8; r++) {
        int cnt = 8 - r;
        if (rem < cnt) { ti = r; tj = r + rem; return; }
        rem -= cnt;
    }
    ti = 0; tj = 0;
}

__global__ void __launch_bounds__(256)
score_part_kernel(const float* __restrict__ w_score)
{
    const int chunk = blockIdx.y;
    const int b = blockIdx.z;
    int ti, tj;
    tile_decode(blockIdx.x, ti, tj);

    __shared__ float hsS[32][132];
    __shared__ float heS[32][132];
    __shared__ float wS[128];

    const int i0 = ti * 32, j0 = tj * 32;
    const int tid = threadIdx.x;
    const int x = tid & 15, y = tid >> 4;
    const int ch = chunk * 128;

    const float* hsBase = d_hs + ((size_t)b * TT + i0) * HH + ch;
    const float* heBase = d_he + ((size_t)b * TT + j0) * HH + ch;

    if (tid < 32)
        *(float4*)&wS[tid * 4] = *(const float4*)&w_score[ch + tid * 4];
#pragma unroll
    for (int q = 0; q < 4; q++) {
        int idx = tid + q * 256;
        int r = idx >> 5;
        int c4 = (idx & 31) * 4;
        *(float4*)&hsS[r][c4] = *(const float4*)&hsBase[(size_t)r * HH + c4];
        *(float4*)&heS[r][c4] = *(const float4*)&heBase[(size_t)r * HH + c4];
    }
    __syncthreads();

    float acc00 = 0.f, acc01 = 0.f, acc10 = 0.f, acc11 = 0.f;
#pragma unroll 4
    for (int c = 0; c < 128; c += 4) {
        float4 w4 = *(float4*)&wS[c];
        float4 hA = *(float4*)&hsS[y][c];
        float4 hB = *(float4*)&hsS[y + 16][c];
        float4 eA = *(float4*)&heS[x][c];
        float4 eB = *(float4*)&heS[x + 16][c];
        acc00 += rdot4(hA, eA, w4);
        acc01 += rdot4(hA, eB, w4);
        acc10 += rdot4(hB, eA, w4);
        acc11 += rdot4(hB, eB, w4);
    }

    float* sp = d_spart[chunk] + (size_t)b * SS;
    const int iA = i0 + y, iB = i0 + y + 16;
    const int jA = j0 + x, jB = j0 + x + 16;

    #define EMITP(ii, jj, av)                                                 \
        if ((jj) >= (ii)) {                                                   \
            int s = (2 * (ii) * TT - (ii) * (ii) + (ii)) / 2 + ((jj) - (ii)); \
            sp[s] = (av);                                                     \
        }
    EMITP(iA, jA, acc00)
    EMITP(iA, jB, acc01)
    EMITP(iB, jA, acc10)
    EMITP(iB, jB, acc11)
    #undef EMITP
}

// reduce partials + bias + mask -> d_scores.  grid (36, 8), 256 thr.
__global__ void __launch_bounds__(256)
score_reduce_kernel(const int* __restrict__ input_mask,
                    const float* __restrict__ b_score)
{
    const int b = blockIdx.y;
    int ti, tj;
    tile_decode(blockIdx.x, ti, tj);
    const int i0 = ti * 32, j0 = tj * 32;
    const int tid = threadIdx.x;
    const int x = tid & 15, y = tid >> 4;
    const float bsc = *b_score;
    const int* mb = input_mask + b * TT;
    const size_t bo = (size_t)b * SS;
    float* out = d_scores + bo;

    #define EMITR(ii, jj)                                                     \
        if ((jj) >= (ii)) {                                                   \
            int s = (2 * (ii) * TT - (ii) * (ii) + (ii)) / 2 + ((jj) - (ii)); \
            float v = d_spart[0][bo + s] + d_spart[1][bo + s]                 \
                    + d_spart[2][bo + s] + d_spart[3][bo + s];                \
            bool ok = mb[(ii)] && mb[(jj)];                                   \
            out[s] = ok ? (v + bsc) : NEGF;                                   \
        }
    EMITR(i0 + y, j0 + x)
    EMITR(i0 + y, j0 + x + 16)
    EMITR(i0 + y + 16, j0 + x)
    EMITR(i0 + y + 16, j0 + x + 16)
    #undef EMITR
}

// =================================================================
// Top-K: parallel radix select (4 x 8-bit) + two-sweep selection
// =================================================================
__device__ __forceinline__ unsigned fkey(float f)
{
    unsigned u = __float_as_uint(f);
    return (u & 0x80000000u) ? ~u : (u | 0x80000000u);
}

__global__ void __launch_bounds__(256)
topk_init_kernel()
{
    const int b = blockIdx.x, t = threadIdx.x;
    d_hist[b][t] = 0u;
    if (t == 0) { d_prefix[b] = 0u; d_R[b] = K_TOP; }
}

// grid (32, BB), 256 threads
__global__ void __launch_bounds__(256)
topk_hist_kernel(int shift)
{
    const int b = blockIdx.y;
    const int tid = threadIdx.x;
    __shared__ unsigned h[256];
    h[tid] = 0u;
    __syncthreads();

    const unsigned mask = (shift == 24) ? 0u : (0xFFFFFFFFu << (shift + 8));
    const unsigned pref = d_prefix[b];
    const float* sc = d_scores + (size_t)b * SS + blockIdx.x * SLICE;
    for (int i = tid; i < SLICE; i += 256) {
        unsigned u = fkey(sc[i]);
        if ((u & mask) == pref)
            atomicAdd(&h[(u >> shift) & 255u], 1u);
    }
    __syncthreads();
    if (h[tid]) atomicAdd(&d_hist[b][tid], h[tid]);
}

// grid (BB), 256 threads: pick digit, update prefix/R, zero hist
__global__ void __launch_bounds__(256)
topk_scan_kernel(int shift)
{
    const int b = blockIdx.x, t = threadIdx.x;
    __shared__ unsigned sh[256];
    unsigned c = d_hist[b][t];
    sh[t] = c;
    __syncthreads();
#pragma unroll
    for (int off = 1; off < 256; off <<= 1) {
        unsigned add = (t + off < 256) ? sh[t + off] : 0u;
        __syncthreads();
        sh[t] += add;
        __syncthreads();
    }
    const unsigned R = (unsigned)d_R[b];
    const unsigned suff = sh[t];
    const unsigned sn = (t < 255) ? sh[t + 1] : 0u;
    if (suff >= R && sn < R) {
        d_prefix[b] |= ((unsigned)t) << shift;
        d_R[b] = (int)(R - sn);
    }
    d_hist[b][t] = 0u;
}

// grid (BB), 1024 threads: two-sweep ordered selection
__global__ void __launch_bounds__(1024)
topk_select_kernel()
{
    const int b = blockIdx.x;
    const int tid = threadIdx.x;
    const int w = tid >> 5, lane = tid & 31;
    const float* sc = d_scores + (size_t)b * SS;
    const unsigned thresh = d_prefix[b];
    const int numEq = d_R[b];

    __shared__ int wcg[32], wce[32], wog[32], woe[32];

    const int base = w * SLICE;
    int cg = 0, ce = 0;
    for (int i0 = 0; i0 < SLICE; i0 += 32) {
        int i = i0 + lane;
        bool valid = i < SLICE;
        unsigned u = valid ? fkey(sc[base + i]) : 0u;
        unsigned bg = __ballot_sync(0xffffffffu, valid && u > thresh);
        unsigned be = __ballot_sync(0xffffffffu, valid && u == thresh);
        cg += __popc(bg);
        ce += __popc(be);
    }
    if (lane == 0) { wcg[w] = cg; wce[w] = ce; }
    __syncthreads();

    if (w == 0) {
        int g = wcg[lane], e = wce[lane];
        int sg = g, se = e;
#pragma unroll
        for (int off = 1; off < 32; off <<= 1) {
            int t1 = __shfl_up_sync(0xffffffffu, sg, off);
            int t2 = __shfl_up_sync(0xffffffffu, se, off);
            if (lane >= off) { sg += t1; se += t2; }
        }
        wog[lane] = sg - g;
        woe[lane] = se - e;
    }
    __syncthreads();

    int rg = wog[w], re = woe[w];
    const unsigned lt = (1u << lane) - 1u;
    for (int i0 = 0; i0 < SLICE; i0 += 32) {
        int i = i0 + lane;
        bool valid = i < SLICE;
        float val = valid ? sc[base + i] : 0.f;
        unsigned u = valid ? fkey(val) : 0u;
        bool g = valid && u > thresh;
        bool e = valid && u == thresh;
        unsigned bg = __ballot_sync(0xffffffffu, g);
        unsigned be = __ballot_sync(0xffffffffu, e);
        if (g || e) {
            int mg = __popc(bg & lt);
            int me = __popc(be & lt);
            int eBefore = re + me;
            bool sel = g || (eBefore < numEq);
            if (sel) {
                int pos = (rg + mg) + min(eBefore, numEq);
                d_topidx[b * K_TOP + pos] = base + i;
                d_toplog[b * K_TOP + pos] = val;
            }
        }
        rg += __popc(bg);
        re += __popc(be);
    }
}

// =================================================================
// Finalize: probs + per-batch BCE partial sums
// =================================================================
__global__ void __launch_bounds__(512)
finalize_kernel(const int* __restrict__ answer_spans, float* __restrict__ out)
{
    const int b = blockIdx.x;
    const int k = threadIdx.x;

    __shared__ int gold[NUM_GOLD];
    __shared__ float red[512];

    if (k < NUM_GOLD) {
        int s0 = answer_spans[(b * NUM_GOLD + k) * 2 + 0];
        int e0 = answer_spans[(b * NUM_GOLD + k) * 2 + 1];
        int idx = (2 * s0 * TT - s0 * s0 + s0) / 2 + (e0 - s0);
        gold[k] = (s0 >= 0) ? idx : -1;
    }
    __syncthreads();

    int s = d_topidx[b * K_TOP + k];
    float l = d_toplog[b * K_TOP + k];
    float m = (l > -1e19f) ? 1.f : 0.f;

    float pred = 0.f;
#pragma unroll
    for (int g = 0; g < NUM_GOLD; g++)
        if (gold[g] == s) pred = 1.f;

    float prob = (1.f / (1.f + expf(-l))) * m;
    out[b * K_TOP + k] = prob;

    float bce = fmaxf(l, 0.f) - l * pred + log1pf(expf(-fabsf(l)));
    red[k] = m * bce;
    __syncthreads();
    for (int st = 256; st > 0; st >>= 1) {
        if (k < st) red[k] += red[k + st];
        __syncthreads();
    }
    if (k == 0) d_losspart[b] = red[0];
}

__global__ void sum_loss_kernel(float* __restrict__ out)
{
    float ssum = 0.f;
    for (int b = 0; b < BB; b++) ssum += d_losspart[b];
    out[BB * K_TOP] = ssum;
}

// =================================================================
// Launch
// =================================================================
extern "C" void kernel_launch(void* const* d_in, const int* in_sizes, int n_in,
                              void* d_out, int out_size)
{
    const float* inputs       = (const float*)d_in[0];
    const int*   input_mask   = (const int*)d_in[1];
    const int*   answer_spans = (const int*)d_in[2];
    const float* W_start      = (const float*)d_in[3];
    const float* b_start      = (const float*)d_in[4];
    const float* W_end        = (const float*)d_in[5];
    const float* b_end        = (const float*)d_in[6];
    const float* w_score      = (const float*)d_in[7];
    const float* b_score      = (const float*)d_in[8];
    float* out = (float*)d_out;

    static int smem_set = 0;
    if (!smem_set) {
        cudaFuncSetAttribute(gemm_mma_kernel,
                             cudaFuncAttributeMaxDynamicSharedMemorySize, GEMM_SMEM);
        smem_set = 1;
    }

    convert_x_kernel<<<(M_TOT * DD / 4) / 256, 256>>>(inputs);

    dim3 gW(HH / 32, DD / 32, 2);
    convert_w_kernel<<<gW, 256>>>(W_start, W_end);

    dim3 gGemm(HH / 128, M_TOT / 128, 2);   // (4, 16, 2)
    gemm_mma_kernel<<<gGemm, 256, GEMM_SMEM>>>(b_start, b_end);

    dim3 gScoreP(36, 4, BB);
    score_part_kernel<<<gScoreP, 256>>>(w_score);

    dim3 gScoreR(36, BB);
    score_reduce_kernel<<<gScoreR, 256>>>(input_mask, b_score);

    topk_init_kernel<<<BB, 256>>>();
    dim3 gHist(32, BB);
    for (int shift = 24; shift >= 0; shift -= 8) {
        topk_hist_kernel<<<gHist, 256>>>(shift);
        topk_scan_kernel<<<BB, 256>>>(shift);
    }
    topk_select_kernel<<<BB, 1024>>>();

    finalize_kernel<<<BB, 512>>>(answer_spans, out);

    sum_loss_kernel<<<1, 1>>>(out);
}

// round 7
// speedup vs baseline: 1.9522x; 1.0389x over previous
#include <cuda_runtime.h>
#include <cuda_bf16.h>
#include <cstdint>
#include <math.h>

#define BB 8
#define TT 256
#define DD 1024
#define HH 512
#define SS 32896      // T*(T+1)/2 = 32*1028
#define K_TOP 512
#define NUM_GOLD 10
#define NEGF (-1e20f)

#define M_TOT (BB * TT)   // 2048
#define SLICE 1028        // SS / 32
#define NCHUNK 8          // score h-chunks of 64

// ---------------- scratch (no allocation allowed) ----------------
__device__ float d_hs[M_TOT * HH];              // 4 MB
__device__ float d_he[M_TOT * HH];              // 4 MB
__device__ float d_spart[NCHUNK][BB * SS];      // 8.4 MB score partials
__device__ float d_scores[BB * SS];             // ~1 MB
__device__ int   d_topidx[BB * K_TOP];
__device__ float d_toplog[BB * K_TOP];
__device__ float d_losspart[BB];
__device__ unsigned d_done;

__device__ unsigned d_hist4[BB][4][256];

__device__ __nv_bfloat16 d_Xh[M_TOT * DD];      // 4 MB
__device__ __nv_bfloat16 d_Xl[M_TOT * DD];      // 4 MB
__device__ __nv_bfloat16 d_Wth[2][HH * DD];     // W^T hi, [n,k]
__device__ __nv_bfloat16 d_Wtl[2][HH * DD];     // W^T lo, [n,k]

// ======================= helpers ============================
__device__ __forceinline__ uint32_t smem_u32(const void* p)
{
    uint32_t a;
    asm("{ .reg .u64 t; cvta.to.shared.u64 t, %1; cvt.u32.u64 %0, t; }"
        : "=r"(a) : "l"(p));
    return a;
}

#define LDSM_X4(r0, r1, r2, r3, addr) \
    asm volatile("ldmatrix.sync.aligned.m8n8.x4.shared.b16 {%0,%1,%2,%3}, [%4];" \
                 : "=r"(r0), "=r"(r1), "=r"(r2), "=r"(r3) : "r"(addr))

#define MMA16816(d, a0, a1, a2, a3, b0, b1) \
    asm volatile("mma.sync.aligned.m16n8k16.row.col.f32.bf16.bf16.f32 " \
                 "{%0,%1,%2,%3}, {%4,%5,%6,%7}, {%8,%9}, {%0,%1,%2,%3};" \
                 : "+f"((d)[0]), "+f"((d)[1]), "+f"((d)[2]), "+f"((d)[3]) \
                 : "r"(a0), "r"(a1), "r"(a2), "r"(a3), "r"(b0), "r"(b1))

#define CP_ASYNC16(saddr, gaddr) \
    asm volatile("cp.async.cg.shared.global [%0], [%1], 16;" \
                 :: "r"(saddr), "l"(gaddr))
#define CP_COMMIT()  asm volatile("cp.async.commit_group;" ::: "memory")
#define CP_WAIT1()   asm volatile("cp.async.wait_group 1;" ::: "memory")
#define CP_WAIT0()   asm volatile("cp.async.wait_group 0;" ::: "memory")

// =================================================================
// Conversion: fp32 -> (bf16 hi, bf16 lo) split
// =================================================================
__global__ void __launch_bounds__(256)
convert_x_kernel(const float* __restrict__ X)
{
    int i = blockIdx.x * 256 + threadIdx.x;      // float4 index
    float4 v = ((const float4*)X)[i];
    __nv_bfloat16 h0 = __float2bfloat16_rn(v.x);
    __nv_bfloat16 h1 = __float2bfloat16_rn(v.y);
    __nv_bfloat16 h2 = __float2bfloat16_rn(v.z);
    __nv_bfloat16 h3 = __float2bfloat16_rn(v.w);
    __nv_bfloat16 l0 = __float2bfloat16_rn(v.x - __bfloat162float(h0));
    __nv_bfloat16 l1 = __float2bfloat16_rn(v.y - __bfloat162float(h1));
    __nv_bfloat16 l2 = __float2bfloat16_rn(v.z - __bfloat162float(h2));
    __nv_bfloat16 l3 = __float2bfloat16_rn(v.w - __bfloat162float(h3));
    ((__nv_bfloat162*)d_Xh)[2 * i]     = __nv_bfloat162(h0, h1);
    ((__nv_bfloat162*)d_Xh)[2 * i + 1] = __nv_bfloat162(h2, h3);
    ((__nv_bfloat162*)d_Xl)[2 * i]     = __nv_bfloat162(l0, l1);
    ((__nv_bfloat162*)d_Xl)[2 * i + 1] = __nv_bfloat162(l2, l3);
}

// transpose W [K=1024, N=512] -> Wt [N, K], split hi/lo.
// block (0,0,0) additionally zeroes the top-k histogram buffers.
__global__ void __launch_bounds__(256)
convert_w_kernel(const float* __restrict__ Ws, const float* __restrict__ We)
{
    if (blockIdx.x == 0 && blockIdx.y == 0 && blockIdx.z == 0) {
        unsigned* h = (unsigned*)d_hist4;
        for (int i = threadIdx.x; i < BB * 4 * 256; i += 256) h[i] = 0u;
    }

    const float* W = blockIdx.z ? We : Ws;
    __nv_bfloat16* oh = d_Wth[blockIdx.z];
    __nv_bfloat16* ol = d_Wtl[blockIdx.z];

    __shared__ float s[32][33];
    const int n0 = blockIdx.x * 32;
    const int k0 = blockIdx.y * 32;
    const int tx = threadIdx.x & 31, ty = threadIdx.x >> 5;   // 32x8

    for (int j = ty; j < 32; j += 8)
        s[j][tx] = W[(size_t)(k0 + j) * HH + n0 + tx];
    __syncthreads();
    for (int j = ty; j < 32; j += 8) {
        float v = s[tx][j];      // W[k0+tx][n0+j]
        __nv_bfloat16 h = __float2bfloat16_rn(v);
        __nv_bfloat16 l = __float2bfloat16_rn(v - __bfloat162float(h));
        size_t o = (size_t)(n0 + j) * DD + k0 + tx;
        oh[o] = h;
        ol[o] = l;
    }
}

// =================================================================
// mma.sync GEMM: CTA tile 128x128, BK=64, 8 warps, cp.async 2-stage,
// 3-product bf16 split.  grid = (4, 16, 2), 256 threads.
// =================================================================
#define SKW_B 144                        // smem row stride bytes
#define BUF_BYTES (128 * SKW_B)          // 18432
#define STAGE_BYTES (4 * BUF_BYTES)      // 73728
#define GEMM_SMEM (2 * STAGE_BYTES)      // 147456

__global__ void __launch_bounds__(256, 1)
gemm_mma_kernel(const float* __restrict__ bias_s, const float* __restrict__ bias_e)
{
    extern __shared__ char smem[];
    const int tid = threadIdx.x, wid = tid >> 5, lane = tid & 31;
    const int which = blockIdx.z;
    const int m0 = blockIdx.y * 128, n0 = blockIdx.x * 128;

    const char* gsrc0[4];
    gsrc0[0] = (const char*)(d_Xh + (size_t)m0 * DD);
    gsrc0[1] = (const char*)(d_Xl + (size_t)m0 * DD);
    gsrc0[2] = (const char*)(d_Wth[which] + (size_t)n0 * DD);
    gsrc0[3] = (const char*)(d_Wtl[which] + (size_t)n0 * DD);

    const int lr = tid >> 3;             // 0..31 (row base; +32 per it)
    const int lc = tid & 7;              // 16B column 0..7

    const int warp_m = wid & 3, warp_n = wid >> 2;
    const int aRowOff = (warp_m * 32 + (lane & 15)) * SKW_B;
    const int aColOff = (lane >> 4) * 16;
    const int bRowOff = (warp_n * 64 + (lane & 7) + ((lane >> 4) << 3)) * SKW_B;
    const int bColOff = ((lane >> 3) & 1) * 16;

    float acc[2][8][4];
#pragma unroll
    for (int mt = 0; mt < 2; mt++)
#pragma unroll
        for (int nt = 0; nt < 8; nt++)
#pragma unroll
            for (int q = 0; q < 4; q++) acc[mt][nt][q] = 0.f;

    const uint32_t sstage[2] = { smem_u32(smem), smem_u32(smem + STAGE_BYTES) };

    #define ISSUE_STAGE(c, stg) do {                                          \
        const int kcB = (c) * 128;                                            \
        _Pragma("unroll")                                                     \
        for (int t = 0; t < 4; t++) {                                         \
            uint32_t sbase = sstage[stg] + t * BUF_BYTES;                     \
            const char* g = gsrc0[t] + kcB;                                   \
            _Pragma("unroll")                                                 \
            for (int it = 0; it < 4; it++) {                                  \
                int r = lr + it * 32;                                         \
                uint32_t sa = sbase + r * SKW_B + lc * 16;                    \
                const char* ga = g + (size_t)r * (DD * 2) + lc * 16;          \
                CP_ASYNC16(sa, ga);                                           \
            }                                                                 \
        }                                                                     \
        CP_COMMIT();                                                          \
    } while (0)

    ISSUE_STAGE(0, 0);

    const int pa[3] = {0, 0, 1};
    const int pb[3] = {2, 3, 2};

    for (int c = 0; c < 16; c++) {
        const int stg = c & 1;
        if (c + 1 < 16) { ISSUE_STAGE(c + 1, stg ^ 1); CP_WAIT1(); }
        else            { CP_WAIT0(); }
        __syncthreads();

        const uint32_t sb = sstage[stg];
#pragma unroll
        for (int kk = 0; kk < 4; kk++) {
#pragma unroll
            for (int p = 0; p < 3; p++) {
                const uint32_t ab = sb + pa[p] * BUF_BYTES + aRowOff + kk * 32 + aColOff;
                uint32_t a0[4], a1[4];
                LDSM_X4(a0[0], a0[1], a0[2], a0[3], ab);
                LDSM_X4(a1[0], a1[1], a1[2], a1[3], ab + 16 * SKW_B);

                const uint32_t bbase = sb + pb[p] * BUF_BYTES + bRowOff + kk * 32 + bColOff;
                uint32_t b[4][4];
#pragma unroll
                for (int ntp = 0; ntp < 4; ntp++)
                    LDSM_X4(b[ntp][0], b[ntp][1], b[ntp][2], b[ntp][3],
                            bbase + ntp * 16 * SKW_B);

#pragma unroll
                for (int nt = 0; nt < 8; nt++) {
                    const uint32_t bb0 = b[nt >> 1][(nt & 1) * 2];
                    const uint32_t bb1 = b[nt >> 1][(nt & 1) * 2 + 1];
                    MMA16816(acc[0][nt], a0[0], a0[1], a0[2], a0[3], bb0, bb1);
                    MMA16816(acc[1][nt], a1[0], a1[1], a1[2], a1[3], bb0, bb1);
                }
            }
        }
        __syncthreads();
    }

    const float* bias = which ? bias_e : bias_s;
    float* C = which ? d_he : d_hs;
    const int row0 = m0 + warp_m * 32 + (lane >> 2);
    const int col0 = n0 + warp_n * 64 + (lane & 3) * 2;
#pragma unroll
    for (int mt = 0; mt < 2; mt++) {
#pragma unroll
        for (int nt = 0; nt < 8; nt++) {
            const int row = row0 + mt * 16;
            const int col = col0 + nt * 8;
            const float b0 = bias[col], b1 = bias[col + 1];
            float2 v0 = { acc[mt][nt][0] + b0, acc[mt][nt][1] + b1 };
            float2 v1 = { acc[mt][nt][2] + b0, acc[mt][nt][3] + b1 };
            *(float2*)&C[(size_t)row * HH + col] = v0;
            *(float2*)&C[(size_t)(row + 8) * HH + col] = v1;
        }
    }
}

// =================================================================
// Span scoring, partial over an h-chunk of 64 channels.
// grid = (36 tiles, 8 chunks, 8 batches), 256 threads, 2x2/thread.
// =================================================================
__device__ __forceinline__ float rdot4(float4 h, float4 e, float4 w)
{
    return fmaxf(h.x + e.x, 0.f) * w.x + fmaxf(h.y + e.y, 0.f) * w.y
         + fmaxf(h.z + e.z, 0.f) * w.z + fmaxf(h.w + e.w, 0.f) * w.w;
}

__device__ __forceinline__ void tile_decode(int bx, int& ti, int& tj)
{
    int rem = bx;
    for (int r = 0; r < 8; r++) {
        int cnt = 8 - r;
        if (rem < cnt) { ti = r; tj = r + rem; return; }
        rem -= cnt;
    }
    ti = 0; tj = 0;
}

__global__ void __launch_bounds__(256)
score_part_kernel(const float* __restrict__ w_score)
{
    const int chunk = blockIdx.y;
    const int b = blockIdx.z;
    int ti, tj;
    tile_decode(blockIdx.x, ti, tj);

    __shared__ float hsS[32][68];
    __shared__ float heS[32][68];
    __shared__ float wS[64];

    const int i0 = ti * 32, j0 = tj * 32;
    const int tid = threadIdx.x;
    const int x = tid & 15, y = tid >> 4;
    const int ch = chunk * 64;

    const float* hsBase = d_hs + ((size_t)b * TT + i0) * HH + ch;
    const float* heBase = d_he + ((size_t)b * TT + j0) * HH + ch;

    if (tid < 16)
        *(float4*)&wS[tid * 4] = *(const float4*)&w_score[ch + tid * 4];
#pragma unroll
    for (int q = 0; q < 2; q++) {
        int idx = tid + q * 256;
        int r = idx >> 4;             // 0..31
        int c4 = (idx & 15) * 4;      // 0..60
        *(float4*)&hsS[r][c4] = *(const float4*)&hsBase[(size_t)r * HH + c4];
        *(float4*)&heS[r][c4] = *(const float4*)&heBase[(size_t)r * HH + c4];
    }
    __syncthreads();

    float acc00 = 0.f, acc01 = 0.f, acc10 = 0.f, acc11 = 0.f;
#pragma unroll
    for (int c = 0; c < 64; c += 4) {
        float4 w4 = *(float4*)&wS[c];
        float4 hA = *(float4*)&hsS[y][c];
        float4 hB = *(float4*)&hsS[y + 16][c];
        float4 eA = *(float4*)&heS[x][c];
        float4 eB = *(float4*)&heS[x + 16][c];
        acc00 += rdot4(hA, eA, w4);
        acc01 += rdot4(hA, eB, w4);
        acc10 += rdot4(hB, eA, w4);
        acc11 += rdot4(hB, eB, w4);
    }

    float* sp = d_spart[chunk] + (size_t)b * SS;
    const int iA = i0 + y, iB = i0 + y + 16;
    const int jA = j0 + x, jB = j0 + x + 16;

    #define EMITP(ii, jj, av)                                                 \
        if ((jj) >= (ii)) {                                                   \
            int s = (2 * (ii) * TT - (ii) * (ii) + (ii)) / 2 + ((jj) - (ii)); \
            sp[s] = (av);                                                     \
        }
    EMITP(iA, jA, acc00)
    EMITP(iA, jB, acc01)
    EMITP(iB, jA, acc10)
    EMITP(iB, jB, acc11)
    #undef EMITP
}

// =================================================================
// Top-K machinery
// =================================================================
__device__ __forceinline__ unsigned fkey(float f)
{
    unsigned u = __float_as_uint(f);
    return (u & 0x80000000u) ? ~u : (u | 0x80000000u);
}

// all threads call; threads <256 do the work; updates prefix/R (uniform)
__device__ void fold_digit(const unsigned* gbuf, int shift,
                           unsigned& prefix, unsigned& R,
                           unsigned* sh, unsigned* shv)
{
    const int t = threadIdx.x;
    if (t < 256) sh[t] = gbuf[t];
    __syncthreads();
    for (int off = 1; off < 256; off <<= 1) {
        unsigned add = 0u;
        if (t < 256 && t + off < 256) add = sh[t + off];
        __syncthreads();
        if (t < 256) sh[t] += add;
        __syncthreads();
    }
    if (t < 256) {
        unsigned suff = sh[t];
        unsigned sn = (t < 255) ? sh[t + 1] : 0u;
        if (suff >= R && sn < R) { shv[0] = (unsigned)t; shv[1] = R - sn; }
    }
    __syncthreads();
    prefix |= shv[0] << (unsigned)shift;
    R = shv[1];
    __syncthreads();
}

// reduce partials + bias + mask -> d_scores, and histogram pass 0.
// grid (36, BB), 256 threads.
__global__ void __launch_bounds__(256)
score_reduce_kernel(const int* __restrict__ input_mask,
                    const float* __restrict__ b_score)
{
    const int b = blockIdx.y;
    int ti, tj;
    tile_decode(blockIdx.x, ti, tj);
    const int i0 = ti * 32, j0 = tj * 32;
    const int tid = threadIdx.x;
    const int x = tid & 15, y = tid >> 4;
    const float bsc = *b_score;
    const int* mb = input_mask + b * TT;
    const size_t bo = (size_t)b * SS;
    float* out = d_scores + bo;

    __shared__ unsigned hloc[256];
    hloc[tid] = 0u;
    __syncthreads();

    #define EMITR(ii, jj)                                                     \
        if ((jj) >= (ii)) {                                                   \
            int s = (2 * (ii) * TT - (ii) * (ii) + (ii)) / 2 + ((jj) - (ii)); \
            float v = 0.f;                                                    \
            _Pragma("unroll")                                                 \
            for (int cq = 0; cq < NCHUNK; cq++) v += d_spart[cq][bo + s];     \
            bool ok = mb[(ii)] && mb[(jj)];                                   \
            float sv = ok ? (v + bsc) : NEGF;                                 \
            out[s] = sv;                                                      \
            atomicAdd(&hloc[fkey(sv) >> 24], 1u);                             \
        }
    EMITR(i0 + y, j0 + x)
    EMITR(i0 + y, j0 + x + 16)
    EMITR(i0 + y + 16, j0 + x)
    EMITR(i0 + y + 16, j0 + x + 16)
    #undef EMITR

    __syncthreads();
    if (hloc[tid]) atomicAdd(&d_hist4[b][0][tid], hloc[tid]);
}

// hist pass (pass = 1..3), folding previous digests locally.
// grid (32, BB), 256 threads.
__global__ void __launch_bounds__(256)
topk_hist_kernel(int pass)
{
    const int b = blockIdx.y;
    const int t = threadIdx.x;
    __shared__ unsigned sh[256];
    __shared__ unsigned shv[2];
    __shared__ unsigned hloc[256];

    unsigned prefix = 0u, R = K_TOP;
    for (int q = 0; q < pass; q++)
        fold_digit(d_hist4[b][q], 24 - 8 * q, prefix, R, sh, shv);

    hloc[t] = 0u;
    __syncthreads();

    const int shift = 24 - 8 * pass;
    const unsigned mask = 0xFFFFFFFFu << (shift + 8);
    const float* sc = d_scores + (size_t)b * SS + blockIdx.x * SLICE;
    for (int i = t; i < SLICE; i += 256) {
        unsigned u = fkey(sc[i]);
        if ((u & mask) == prefix)
            atomicAdd(&hloc[(u >> shift) & 255u], 1u);
    }
    __syncthreads();
    if (hloc[t]) atomicAdd(&d_hist4[b][pass][t], hloc[t]);
}

// grid (BB), 1024 threads: fold all digests, then two-sweep selection.
__global__ void __launch_bounds__(1024)
topk_select_kernel()
{
    const int b = blockIdx.x;
    const int tid = threadIdx.x;
    const int w = tid >> 5, lane = tid & 31;

    __shared__ unsigned sh[256];
    __shared__ unsigned shv[2];
    __shared__ int wcg[32], wce[32], wog[32], woe[32];

    unsigned prefix = 0u, R = K_TOP;
    for (int q = 0; q < 4; q++)
        fold_digit(d_hist4[b][q], 24 - 8 * q, prefix, R, sh, shv);

    const unsigned thresh = prefix;
    const int numEq = (int)R;
    const float* sc = d_scores + (size_t)b * SS;

    const int base = w * SLICE;
    int cg = 0, ce = 0;
    for (int i0 = 0; i0 < SLICE; i0 += 32) {
        int i = i0 + lane;
        bool valid = i < SLICE;
        unsigned u = valid ? fkey(sc[base + i]) : 0u;
        unsigned bg = __ballot_sync(0xffffffffu, valid && u > thresh);
        unsigned be = __ballot_sync(0xffffffffu, valid && u == thresh);
        cg += __popc(bg);
        ce += __popc(be);
    }
    if (lane == 0) { wcg[w] = cg; wce[w] = ce; }
    __syncthreads();

    if (w == 0) {
        int g = wcg[lane], e = wce[lane];
        int sg = g, se = e;
#pragma unroll
        for (int off = 1; off < 32; off <<= 1) {
            int t1 = __shfl_up_sync(0xffffffffu, sg, off);
            int t2 = __shfl_up_sync(0xffffffffu, se, off);
            if (lane >= off) { sg += t1; se += t2; }
        }
        wog[lane] = sg - g;
        woe[lane] = se - e;
    }
    __syncthreads();

    int rg = wog[w], re = woe[w];
    const unsigned lt = (1u << lane) - 1u;
    for (int i0 = 0; i0 < SLICE; i0 += 32) {
        int i = i0 + lane;
        bool valid = i < SLICE;
        float val = valid ? sc[base + i] : 0.f;
        unsigned u = valid ? fkey(val) : 0u;
        bool g = valid && u > thresh;
        bool e = valid && u == thresh;
        unsigned bg = __ballot_sync(0xffffffffu, g);
        unsigned be = __ballot_sync(0xffffffffu, e);
        if (g || e) {
            int mg = __popc(bg & lt);
            int me = __popc(be & lt);
            int eBefore = re + me;
            bool sel = g || (eBefore < numEq);
            if (sel) {
                int pos = (rg + mg) + min(eBefore, numEq);
                d_topidx[b * K_TOP + pos] = base + i;
                d_toplog[b * K_TOP + pos] = val;
            }
        }
        rg += __popc(bg);
        re += __popc(be);
    }
}

// =================================================================
// Finalize: probs + BCE; last block does the deterministic loss sum.
// =================================================================
__global__ void __launch_bounds__(512)
finalize_kernel(const int* __restrict__ answer_spans, float* __restrict__ out)
{
    const int b = blockIdx.x;
    const int k = threadIdx.x;

    __shared__ int gold[NUM_GOLD];
    __shared__ float red[512];

    if (k < NUM_GOLD) {
        int s0 = answer_spans[(b * NUM_GOLD + k) * 2 + 0];
        int e0 = answer_spans[(b * NUM_GOLD + k) * 2 + 1];
        int idx = (2 * s0 * TT - s0 * s0 + s0) / 2 + (e0 - s0);
        gold[k] = (s0 >= 0) ? idx : -1;
    }
    __syncthreads();

    int s = d_topidx[b * K_TOP + k];
    float l = d_toplog[b * K_TOP + k];
    float m = (l > -1e19f) ? 1.f : 0.f;

    float pred = 0.f;
#pragma unroll
    for (int g = 0; g < NUM_GOLD; g++)
        if (gold[g] == s) pred = 1.f;

    float prob = (1.f / (1.f + expf(-l))) * m;
    out[b * K_TOP + k] = prob;

    float bce = fmaxf(l, 0.f) - l * pred + log1pf(expf(-fabsf(l)));
    red[k] = m * bce;
    __syncthreads();
    for (int st = 256; st > 0; st >>= 1) {
        if (k < st) red[k] += red[k + st];
        __syncthreads();
    }
    if (k == 0) {
        d_losspart[b] = red[0];
        __threadfence();
        unsigned t = atomicAdd(&d_done, 1u);
        if (t == BB - 1) {
            float ssum = 0.f;
            for (int q = 0; q < BB; q++) ssum += d_losspart[q];
            out[BB * K_TOP] = ssum;
            d_done = 0u;      // self-reset for the next replay
        }
    }
}

// =================================================================
// Launch — 10 graph nodes total
// =================================================================
extern "C" void kernel_launch(void* const* d_in, const int* in_sizes, int n_in,
                              void* d_out, int out_size)
{
    const float* inputs       = (const float*)d_in[0];
    const int*   input_mask   = (const int*)d_in[1];
    const int*   answer_spans = (const int*)d_in[2];
    const float* W_start      = (const float*)d_in[3];
    const float* b_start      = (const float*)d_in[4];
    const float* W_end        = (const float*)d_in[5];
    const float* b_end        = (const float*)d_in[6];
    const float* w_score      = (const float*)d_in[7];
    const float* b_score      = (const float*)d_in[8];
    float* out = (float*)d_out;

    static int smem_set = 0;
    if (!smem_set) {
        cudaFuncSetAttribute(gemm_mma_kernel,
                             cudaFuncAttributeMaxDynamicSharedMemorySize, GEMM_SMEM);
        smem_set = 1;
    }

    convert_x_kernel<<<(M_TOT * DD / 4) / 256, 256>>>(inputs);

    dim3 gW(HH / 32, DD / 32, 2);
    convert_w_kernel<<<gW, 256>>>(W_start, W_end);

    dim3 gGemm(HH / 128, M_TOT / 128, 2);   // (4, 16, 2)
    gemm_mma_kernel<<<gGemm, 256, GEMM_SMEM>>>(b_start, b_end);

    dim3 gScoreP(36, NCHUNK, BB);
    score_part_kernel<<<gScoreP, 256>>>(w_score);

    dim3 gScoreR(36, BB);
    score_reduce_kernel<<<gScoreR, 256>>>(input_mask, b_score);

    dim3 gHist(32, BB);
    topk_hist_kernel<<<gHist, 256>>>(1);
    topk_hist_kernel<<<gHist, 256>>>(2);
    topk_hist_kernel<<<gHist, 256>>>(3);

    topk_select_kernel<<<BB, 1024>>>();

    finalize_kernel<<<BB, 512>>>(answer_spans, out);
}